// round 10
// baseline (speedup 1.0000x reference)
#include <cuda_runtime.h>
#include <cuda_fp16.h>
#include <cstdint>
#include <cstddef>

// ---------------- problem constants ----------------
#define MROWS 16384            // B*T
#define DM    2048             // d_model (K)
#define QSZ   33554432u
#define KSZ   8388608u
#define TLEN  8192

// ---------------- tiling ----------------
#define BM 256
#define BN 128
#define BK 64
#define NCHUNK (DM/BK)                 // 32
#define STG_BYTES 49152                // A 32KB (256x128B) + B 16KB (128x128B)
#define NSTAGE 4
#define SMEM_BYTES (NSTAGE*STG_BYTES)  // 196608; epilogue reuse 256*132*4=135168
#define EPROW 132

// ---------------- device scratch (fp16), 16B-aligned ----------------
__device__ float4 g_A[(size_t)MROWS * DM / 8];   // 64MB as half
__device__ float4 g_B[(size_t)3072  * DM / 8];   // 12MB as half
__device__ float2 g_rope[TLEN * 64];

// ---------------- helpers ----------------
__device__ __forceinline__ uint32_t smem_u32(const void* p) {
    uint32_t a;
    asm("{ .reg .u64 t; cvta.to.shared.u64 t, %1; cvt.u32.u64 %0, t; }" : "=r"(a) : "l"(p));
    return a;
}
__device__ __forceinline__ void cp16(uint32_t dst, const void* src) {
    asm volatile("cp.async.cg.shared.global [%0], [%1], 16;" :: "r"(dst), "l"(src));
}
#define LDSM4(r0,r1,r2,r3,addr) \
    asm volatile("ldmatrix.sync.aligned.m8n8.x4.shared.b16 {%0,%1,%2,%3}, [%4];" \
                 : "=r"(r0), "=r"(r1), "=r"(r2), "=r"(r3) : "r"(addr))
__device__ __forceinline__ void mma16(float* c, const uint32_t* a, uint32_t b0, uint32_t b1) {
    asm volatile(
        "mma.sync.aligned.m16n8k16.row.col.f32.f16.f16.f32 "
        "{%0,%1,%2,%3}, {%4,%5,%6,%7}, {%8,%9}, {%0,%1,%2,%3};"
        : "+f"(c[0]), "+f"(c[1]), "+f"(c[2]), "+f"(c[3])
        : "r"(a[0]), "r"(a[1]), "r"(a[2]), "r"(a[3]), "r"(b0), "r"(b1));
}
__device__ __forceinline__ uint2 cvt4(float4 v) {
    __half2 h0 = __floats2half2_rn(v.x, v.y);
    __half2 h1 = __floats2half2_rn(v.z, v.w);
    uint2 o;
    o.x = *reinterpret_cast<uint32_t*>(&h0);
    o.y = *reinterpret_cast<uint32_t*>(&h1);
    return o;
}

// ---------------- convert X: fp32 -> fp16, 4 x float4/thread ----------------
__global__ void k_cvtx(const float4* __restrict__ s, int n4) {
    uint2* d = (uint2*)g_A;
    int i0 = (blockIdx.x * 512 + threadIdx.x) * 4;
    if (i0 + 3 < n4) {
        float4 v0 = s[i0], v1 = s[i0 + 1], v2 = s[i0 + 2], v3 = s[i0 + 3];
        d[i0] = cvt4(v0); d[i0 + 1] = cvt4(v1); d[i0 + 2] = cvt4(v2); d[i0 + 3] = cvt4(v3);
    } else {
        for (int i = i0; i < n4; i++) d[i] = cvt4(s[i]);
    }
}

// ---------------- convert weights: wq|wk|wv -> g_B, one launch ----------------
__global__ void k_cvtw(const float4* __restrict__ wq, const float4* __restrict__ wk,
                       const float4* __restrict__ wv) {
    int i = blockIdx.x * 512 + threadIdx.x;            // grid 3072
    uint2* d = (uint2*)g_B;
    const float4* s;
    int j = i;
    if (i < 1048576)        { s = wq; }
    else if (i < 1310720)   { s = wk; j = i - 1048576; }
    else                    { s = wv; j = i - 1310720; }
    d[i] = cvt4(s[j]);
}

// ---------------- RoPE table, FP64-free ----------------
__global__ void k_rope(const int* __restrict__ po) {
    int t = blockIdx.x, j = threadIdx.x;                       // t<8192, j<64
    float invf = exp2f(-(float)j * 0.20762050593046013f);      // log2(10000)/64
    float ang = (float)(t + *po) * invf;
    float k = rintf(ang * 0.15915494309189535f);
    float r = fmaf(-k, 6.28125f, ang);
    r = fmaf(-k, (float)(6.283185307179586 - 6.28125), r);
    float s, c;
    sincosf(r, &s, &c);
    g_rope[t * 64 + j] = make_float2(c, s);
}

// ---------------- stage fill: one 64-wide K chunk (512 threads) ----------------
__device__ __forceinline__ void fill_stage(int tid, const __half* Ab, const __half* Bb,
                                           uint32_t sb, int chunk) {
    const int kof = chunk * BK;
#pragma unroll
    for (int i = 0; i < 4; i++) {                // A: 256 rows x 8 segs = 2048
        int id = i * 512 + tid;
        int r = id >> 3, seg = id & 7;
        uint32_t off = (uint32_t)(r * 128) + (uint32_t)((seg * 16) ^ ((r & 7) << 4));
        cp16(sb + off, Ab + (size_t)r * DM + kof + seg * 8);
    }
#pragma unroll
    for (int i = 0; i < 2; i++) {                // B: 128 rows x 8 segs = 1024
        int id = i * 512 + tid;
        int r = id >> 3, seg = id & 7;
        uint32_t off = (uint32_t)(r * 128) + (uint32_t)((seg * 16) ^ ((r & 7) << 4));
        cp16(sb + 32768u + off, Bb + (size_t)r * DM + kof + seg * 8);
    }
    asm volatile("cp.async.commit_group;" ::: "memory");
}

// ---------------- main GEMM + RoPE epilogue ----------------
__global__ void __launch_bounds__(512, 1)
k_gemm(float* __restrict__ out) {
    extern __shared__ float sm[];
    const uint32_t smb = smem_u32(sm);
    const int tid = threadIdx.x;
    const int lane = tid & 31, wid = tid >> 5;       // 16 warps
    const int q = lane >> 2, t4 = lane & 3;
    const int mw = (wid >> 2) * 64, nw = (wid & 3) * 32;   // warp tile 64x32, grid 4x4
    const int nt = blockIdx.x, mt = blockIdx.y;

    const __half* Ab = (const __half*)g_A + (size_t)mt * BM * DM;
    const __half* Bb = (const __half*)g_B + (size_t)nt * BN * DM;

    float acc[4][4][4];
#pragma unroll
    for (int i = 0; i < 4; i++)
#pragma unroll
        for (int j = 0; j < 4; j++)
#pragma unroll
            for (int r = 0; r < 4; r++) acc[i][j][r] = 0.f;

    fill_stage(tid, Ab, Bb, smb, 0);
    fill_stage(tid, Ab, Bb, smb + STG_BYTES, 1);
    fill_stage(tid, Ab, Bb, smb + 2 * STG_BYTES, 2);

    // per-lane ldmatrix source rows/segs
    const int arow = mw + (lane & 15);               // + mi*16
    const int alds = (lane >> 4);                    // seg +0/+1
    const int brow = nw + ((lane >> 4) << 3) + (lane & 7);   // + np*16
    const int blds = ((lane >> 3) & 1);

    for (int k = 0; k < NCHUNK; k++) {
        const int rem = (NCHUNK - 1) - k;
        if (rem >= 2)      asm volatile("cp.async.wait_group 2;" ::: "memory");
        else if (rem == 1) asm volatile("cp.async.wait_group 1;" ::: "memory");
        else               asm volatile("cp.async.wait_group 0;" ::: "memory");
        __syncthreads();                              // chunk k resident; compute(k-1) done
        if (k + 3 < NCHUNK)                           // slot (k+3)%4 == (k-1)%4: free
            fill_stage(tid, Ab, Bb, smb + (uint32_t)((k + 3) % 4) * STG_BYTES, k + 3);

        const uint32_t Asb = smb + (uint32_t)(k % 4) * STG_BYTES;
        const uint32_t Bsb = Asb + 32768u;
#pragma unroll
        for (int ks = 0; ks < 4; ks++) {
            const uint32_t asw = (uint32_t)(((ks * 2 + alds) * 16) ^ ((arow & 7) << 4));
            const uint32_t bsw = (uint32_t)(((ks * 2 + blds) * 16) ^ ((brow & 7) << 4));
            uint32_t a[4][4], b[4][2];
#pragma unroll
            for (int mi = 0; mi < 4; mi++) {
                uint32_t ad = Asb + (uint32_t)((arow + mi * 16) * 128) + asw;
                LDSM4(a[mi][0], a[mi][1], a[mi][2], a[mi][3], ad);
            }
#pragma unroll
            for (int np = 0; np < 2; np++) {
                uint32_t bd = Bsb + (uint32_t)((brow + np * 16) * 128) + bsw;
                LDSM4(b[2*np][0], b[2*np][1], b[2*np+1][0], b[2*np+1][1], bd);
            }
#pragma unroll
            for (int mi = 0; mi < 4; mi++)
#pragma unroll
                for (int ni = 0; ni < 4; ni++)
                    mma16(acc[mi][ni], a[mi], b[ni][0], b[ni][1]);
        }
    }
    __syncthreads();

    // ---- accum -> padded smem [256][EPROW] ----
#pragma unroll
    for (int mi = 0; mi < 4; mi++) {
        const int r0 = mw + mi * 16 + q;
#pragma unroll
        for (int ni = 0; ni < 4; ni++) {
            const int col = nw + ni * 8 + 2 * t4;
            *(float2*)&sm[r0 * EPROW + col]       = make_float2(acc[mi][ni][0], acc[mi][ni][1]);
            *(float2*)&sm[(r0 + 8) * EPROW + col] = make_float2(acc[mi][ni][2], acc[mi][ni][3]);
        }
    }
    __syncthreads();

    // ---- RoPE + transpose-store (16 lanes cover one row; 2 rows/warp/iter) ----
    const int sub = lane >> 4, l16 = lane & 15;
    const bool ropef = (nt < 20);
    const int d0 = l16 * 4;
#pragma unroll
    for (int it = 0; it < 8; it++) {
        const int row = wid * 16 + it * 2 + sub;
        const int gm = mt * BM + row;
        const int bb = gm >> 13, tt = gm & (TLEN - 1);
        size_t obase;
        if (nt < 16)      obase = ((size_t)(bb * 16 + nt) * TLEN + tt) * 128;
        else if (nt < 20) obase = QSZ + ((size_t)(bb * 4 + (nt - 16)) * TLEN + tt) * 128;
        else              obase = QSZ + KSZ + ((size_t)(bb * 4 + (nt - 20)) * TLEN + tt) * 128;
        float* op = out + obase;
        const float* er = sm + row * EPROW;
        float4 lo = *(const float4*)&er[d0];
        float4 hi = *(const float4*)&er[d0 + 64];
        if (ropef) {
            const float2* rp = g_rope + (size_t)tt * 64 + d0;
            float2 cs0 = rp[0], cs1 = rp[1], cs2 = rp[2], cs3 = rp[3];
            float4 nl, nh;
            nl.x = lo.x * cs0.x - hi.x * cs0.y;  nh.x = hi.x * cs0.x + lo.x * cs0.y;
            nl.y = lo.y * cs1.x - hi.y * cs1.y;  nh.y = hi.y * cs1.x + lo.y * cs1.y;
            nl.z = lo.z * cs2.x - hi.z * cs2.y;  nh.z = hi.z * cs2.x + lo.z * cs2.y;
            nl.w = lo.w * cs3.x - hi.w * cs3.y;  nh.w = hi.w * cs3.x + lo.w * cs3.y;
            lo = nl; hi = nh;
        }
        *(float4*)&op[d0]      = lo;
        *(float4*)&op[d0 + 64] = hi;
    }
}

// ---------------- launch ----------------
extern "C" void kernel_launch(void* const* d_in, const int* in_sizes, int n_in,
                              void* d_out, int out_size) {
    const float* x  = (const float*)d_in[0];
    const float* wq = (const float*)d_in[1];
    const float* wk = (const float*)d_in[2];
    const float* wv = (const float*)d_in[3];
    const int*   po = (const int*)d_in[4];
    float* out = (float*)d_out;

    const int n4x = (MROWS * DM) / 4;      // 8388608 = 4096 * 512 * 4
    k_cvtx<<<4096, 512>>>((const float4*)x, n4x);
    k_cvtw<<<3072, 512>>>((const float4*)wq, (const float4*)wk, (const float4*)wv);
    k_rope<<<TLEN, 64>>>(po);

    cudaFuncSetAttribute(k_gemm, cudaFuncAttributeMaxDynamicSharedMemorySize, SMEM_BYTES);
    k_gemm<<<dim3(24, 64, 1), 512, SMEM_BYTES>>>(out);
    (void)in_sizes; (void)n_in; (void)out_size;
}

// round 11
// speedup vs baseline: 1.1590x; 1.1590x over previous
#include <cuda_runtime.h>
#include <cuda_fp16.h>
#include <cstdint>
#include <cstddef>

// ---------------- problem constants ----------------
#define MROWS 16384            // B*T
#define DM    2048             // d_model (K)
#define QSZ   33554432u
#define KSZ   8388608u
#define TLEN  8192

// ---------------- tiling (R9-proven: 2 CTAs/SM, depth-3) ----------------
#define BM 128
#define BN 128
#define BK 64
#define NCHUNK (DM/BK)                 // 32
#define STG_BYTES 32768                // A 16KB (128x128B) + B 16KB
#define SMEM_BYTES 98304               // 3 stages; epilogue reuse 128*132*4
#define EPROW 132

// ---------------- device scratch (fp16), 16B-aligned ----------------
__device__ float4 g_A[(size_t)MROWS * DM / 8];   // 64MB as half
__device__ float4 g_B[(size_t)3072  * DM / 8];   // 12MB as half
__device__ float2 g_rope[TLEN * 64];

// ---------------- helpers ----------------
__device__ __forceinline__ uint32_t smem_u32(const void* p) {
    uint32_t a;
    asm("{ .reg .u64 t; cvta.to.shared.u64 t, %1; cvt.u32.u64 %0, t; }" : "=r"(a) : "l"(p));
    return a;
}
__device__ __forceinline__ void cp16(uint32_t dst, const void* src) {
    asm volatile("cp.async.cg.shared.global [%0], [%1], 16;" :: "r"(dst), "l"(src));
}
#define LDSM4(r0,r1,r2,r3,addr) \
    asm volatile("ldmatrix.sync.aligned.m8n8.x4.shared.b16 {%0,%1,%2,%3}, [%4];" \
                 : "=r"(r0), "=r"(r1), "=r"(r2), "=r"(r3) : "r"(addr))
__device__ __forceinline__ void mma16(float* c, const uint32_t* a, uint32_t b0, uint32_t b1) {
    asm volatile(
        "mma.sync.aligned.m16n8k16.row.col.f32.f16.f16.f32 "
        "{%0,%1,%2,%3}, {%4,%5,%6,%7}, {%8,%9}, {%0,%1,%2,%3};"
        : "+f"(c[0]), "+f"(c[1]), "+f"(c[2]), "+f"(c[3])
        : "r"(a[0]), "r"(a[1]), "r"(a[2]), "r"(a[3]), "r"(b0), "r"(b1));
}
__device__ __forceinline__ uint2 cvt4(float4 v) {
    __half2 h0 = __floats2half2_rn(v.x, v.y);
    __half2 h1 = __floats2half2_rn(v.z, v.w);
    uint2 o;
    o.x = *reinterpret_cast<uint32_t*>(&h0);
    o.y = *reinterpret_cast<uint32_t*>(&h1);
    return o;
}

// ---------------- merged prelude: cvtx | cvtw | rope in one launch ----------------
// blocks [0,4096): X convert, 4 x float4/thread
// blocks [4096,5632): W convert, 2 x float4/thread
// blocks [5632,6656): rope table, 1 entry/thread
__global__ void __launch_bounds__(512)
k_pre(const float4* __restrict__ x, const float4* __restrict__ wq,
      const float4* __restrict__ wk, const float4* __restrict__ wv,
      const int* __restrict__ po) {
    const int b = blockIdx.x, tid = threadIdx.x;
    if (b < 4096) {
        uint2* d = (uint2*)g_A;
        int i0 = (b * 512 + tid) * 4;                 // covers 8388608 exactly
        float4 v0 = x[i0], v1 = x[i0 + 1], v2 = x[i0 + 2], v3 = x[i0 + 3];
        d[i0] = cvt4(v0); d[i0 + 1] = cvt4(v1); d[i0 + 2] = cvt4(v2); d[i0 + 3] = cvt4(v3);
    } else if (b < 5632) {
        uint2* d = (uint2*)g_B;
        int i0 = (b - 4096) * 1024 + tid * 2;         // covers 1572864 exactly
#pragma unroll
        for (int u = 0; u < 2; u++) {
            int i = i0 + u, j = i;
            const float4* s;
            if (i < 1048576)      { s = wq; }
            else if (i < 1310720) { s = wk; j = i - 1048576; }
            else                  { s = wv; j = i - 1310720; }
            d[i] = cvt4(s[j]);
        }
    } else {
        int idx = (b - 5632) * 512 + tid;             // 524288 = 8192*64
        int t = idx >> 6, j = idx & 63;
        float invf = exp2f(-(float)j * 0.20762050593046013f);   // log2(10000)/64
        float ang = (float)(t + *po) * invf;
        float k = rintf(ang * 0.15915494309189535f);
        float r = fmaf(-k, 6.28125f, ang);
        r = fmaf(-k, (float)(6.283185307179586 - 6.28125), r);
        float s, c;
        sincosf(r, &s, &c);
        g_rope[t * 64 + j] = make_float2(c, s);
    }
}

// ---------------- stage fill: one 64-wide K chunk (fp16) ----------------
__device__ __forceinline__ void fill_stage(int tid, const __half* Ab, const __half* Bb,
                                           uint32_t sb, int chunk) {
    const int kof = chunk * BK;
#pragma unroll
    for (int i = 0; i < 4; i++) {                // A: 128 rows x 8 segs
        int id = i * 256 + tid;
        int r = id >> 3, seg = id & 7;
        uint32_t off = (uint32_t)(r * 128) + (uint32_t)((seg * 16) ^ ((r & 7) << 4));
        cp16(sb + off, Ab + (size_t)r * DM + kof + seg * 8);
    }
#pragma unroll
    for (int i = 0; i < 4; i++) {                // B: 128 rows x 8 segs
        int id = i * 256 + tid;
        int r = id >> 3, seg = id & 7;
        uint32_t off = (uint32_t)(r * 128) + (uint32_t)((seg * 16) ^ ((r & 7) << 4));
        cp16(sb + 16384u + off, Bb + (size_t)r * DM + kof + seg * 8);
    }
    asm volatile("cp.async.commit_group;" ::: "memory");
}

// ---------------- main GEMM + RoPE epilogue ----------------
__global__ void __launch_bounds__(256, 2)
k_gemm(float* __restrict__ out) {
    extern __shared__ float sm[];
    const uint32_t smb = smem_u32(sm);
    const int tid = threadIdx.x;
    const int lane = tid & 31, wid = tid >> 5;      // 8 warps
    const int q = lane >> 2, t4 = lane & 3;
    const int mw = (wid >> 2) * 64, nw = (wid & 3) * 32;   // warp tile 64x32
    const int nt = blockIdx.x, mt = blockIdx.y;

    const __half* Ab = (const __half*)g_A + (size_t)mt * BM * DM;
    const __half* Bb = (const __half*)g_B + (size_t)nt * BN * DM;

    float acc[4][4][4];
#pragma unroll
    for (int i = 0; i < 4; i++)
#pragma unroll
        for (int j = 0; j < 4; j++)
#pragma unroll
            for (int r = 0; r < 4; r++) acc[i][j][r] = 0.f;

    fill_stage(tid, Ab, Bb, smb, 0);
    fill_stage(tid, Ab, Bb, smb + STG_BYTES, 1);
    fill_stage(tid, Ab, Bb, smb + 2 * STG_BYTES, 2);

    // per-lane ldmatrix source rows/segs
    const int arow = mw + (lane & 15);               // + mi*16
    const int alds = (lane >> 4);                    // seg +0/+1
    const int brow = nw + ((lane >> 4) << 3) + (lane & 7);   // + np*16
    const int blds = ((lane >> 3) & 1);

    for (int k = 0; k < NCHUNK; k++) {
        const int s = k % 3;
        const int rem = (NCHUNK - 1) - k;
        if (rem >= 2)      asm volatile("cp.async.wait_group 2;" ::: "memory");
        else if (rem == 1) asm volatile("cp.async.wait_group 1;" ::: "memory");
        else               asm volatile("cp.async.wait_group 0;" ::: "memory");
        __syncthreads();

        const uint32_t Asb = smb + (uint32_t)s * STG_BYTES;
        const uint32_t Bsb = Asb + 16384u;

        // software-pipelined k-steps: prefetch next A frags during HMMAs
        uint32_t a_cur[4][4];
        {
            const uint32_t asw0 = (uint32_t)((alds * 16) ^ ((arow & 7) << 4));
#pragma unroll
            for (int mi = 0; mi < 4; mi++) {
                uint32_t ad = Asb + (uint32_t)((arow + mi * 16) * 128) + asw0;
                LDSM4(a_cur[mi][0], a_cur[mi][1], a_cur[mi][2], a_cur[mi][3], ad);
            }
        }
#pragma unroll
        for (int ks = 0; ks < 4; ks++) {
            const uint32_t bsw = (uint32_t)(((ks * 2 + blds) * 16) ^ ((brow & 7) << 4));
            uint32_t b[4][2];
#pragma unroll
            for (int np = 0; np < 2; np++) {
                uint32_t bd = Bsb + (uint32_t)((brow + np * 16) * 128) + bsw;
                LDSM4(b[2*np][0], b[2*np][1], b[2*np+1][0], b[2*np+1][1], bd);
            }
            uint32_t a_nxt[4][4];
            if (ks < 3) {
                const uint32_t aswn = (uint32_t)((((ks + 1) * 2 + alds) * 16) ^ ((arow & 7) << 4));
#pragma unroll
                for (int mi = 0; mi < 4; mi++) {
                    uint32_t ad = Asb + (uint32_t)((arow + mi * 16) * 128) + aswn;
                    LDSM4(a_nxt[mi][0], a_nxt[mi][1], a_nxt[mi][2], a_nxt[mi][3], ad);
                }
            }
#pragma unroll
            for (int mi = 0; mi < 4; mi++)
#pragma unroll
                for (int ni = 0; ni < 4; ni++)
                    mma16(acc[mi][ni], a_cur[mi], b[ni][0], b[ni][1]);
            if (ks < 3) {
#pragma unroll
                for (int mi = 0; mi < 4; mi++)
#pragma unroll
                    for (int r = 0; r < 4; r++) a_cur[mi][r] = a_nxt[mi][r];
            }
        }
        __syncthreads();
        if (k + 3 < NCHUNK) fill_stage(tid, Ab, Bb, smb + (uint32_t)((k + 3) % 3) * STG_BYTES, k + 3);
    }
    __syncthreads();

    // ---- accum -> padded smem [128][EPROW] ----
#pragma unroll
    for (int mi = 0; mi < 4; mi++) {
        const int r0 = mw + mi * 16 + q;
#pragma unroll
        for (int ni = 0; ni < 4; ni++) {
            const int col = nw + ni * 8 + 2 * t4;
            *(float2*)&sm[r0 * EPROW + col]       = make_float2(acc[mi][ni][0], acc[mi][ni][1]);
            *(float2*)&sm[(r0 + 8) * EPROW + col] = make_float2(acc[mi][ni][2], acc[mi][ni][3]);
        }
    }
    __syncthreads();

    // ---- RoPE + transpose-store (coalesced: 16 lanes cover one row) ----
    const int sub = lane >> 4, l16 = lane & 15;
    const bool ropef = (nt < 20);
    const int d0 = l16 * 4;
#pragma unroll
    for (int it = 0; it < 8; it++) {
        const int row = wid * 16 + it * 2 + sub;
        const int gm = mt * BM + row;
        const int bb = gm >> 13, tt = gm & (TLEN - 1);
        size_t obase;
        if (nt < 16)      obase = ((size_t)(bb * 16 + nt) * TLEN + tt) * 128;
        else if (nt < 20) obase = QSZ + ((size_t)(bb * 4 + (nt - 16)) * TLEN + tt) * 128;
        else              obase = QSZ + KSZ + ((size_t)(bb * 4 + (nt - 20)) * TLEN + tt) * 128;
        float* op = out + obase;
        const float* er = sm + row * EPROW;
        float4 lo = *(const float4*)&er[d0];
        float4 hi = *(const float4*)&er[d0 + 64];
        if (ropef) {
            const float2* rp = g_rope + (size_t)tt * 64 + d0;
            float2 cs0 = rp[0], cs1 = rp[1], cs2 = rp[2], cs3 = rp[3];
            float4 nl, nh;
            nl.x = lo.x * cs0.x - hi.x * cs0.y;  nh.x = hi.x * cs0.x + lo.x * cs0.y;
            nl.y = lo.y * cs1.x - hi.y * cs1.y;  nh.y = hi.y * cs1.x + lo.y * cs1.y;
            nl.z = lo.z * cs2.x - hi.z * cs2.y;  nh.z = hi.z * cs2.x + lo.z * cs2.y;
            nl.w = lo.w * cs3.x - hi.w * cs3.y;  nh.w = hi.w * cs3.x + lo.w * cs3.y;
            lo = nl; hi = nh;
        }
        *(float4*)&op[d0]      = lo;
        *(float4*)&op[d0 + 64] = hi;
    }
}

// ---------------- launch ----------------
extern "C" void kernel_launch(void* const* d_in, const int* in_sizes, int n_in,
                              void* d_out, int out_size) {
    const float* x  = (const float*)d_in[0];
    const float* wq = (const float*)d_in[1];
    const float* wk = (const float*)d_in[2];
    const float* wv = (const float*)d_in[3];
    const int*   po = (const int*)d_in[4];
    float* out = (float*)d_out;

    k_pre<<<6656, 512>>>((const float4*)x, (const float4*)wq,
                         (const float4*)wk, (const float4*)wv, po);

    cudaFuncSetAttribute(k_gemm, cudaFuncAttributeMaxDynamicSharedMemorySize, SMEM_BYTES);
    k_gemm<<<dim3(24, 128, 1), 256, SMEM_BYTES>>>(out);
    (void)in_sizes; (void)n_in; (void)out_size;
}

// round 12
// speedup vs baseline: 1.1618x; 1.0025x over previous
#include <cuda_runtime.h>
#include <cuda_fp16.h>
#include <cstdint>
#include <cstddef>

// ---------------- problem constants ----------------
#define MROWS 16384            // B*T
#define DM    2048             // d_model (K)
#define QSZ   33554432u
#define KSZ   8388608u
#define TLEN  8192

// ---------------- tiling (2 CTAs/SM, depth-3, BK=64: proven) ----------------
#define BM 128
#define BN 128
#define BK 64
#define NCHUNK (DM/BK)                 // 32
#define STG_BYTES 32768                // A 16KB (128x128B) + B 16KB
#define SMEM_BYTES 98304               // 3 stages

// ---------------- device scratch (fp16), 16B-aligned ----------------
__device__ float4 g_A[(size_t)MROWS * DM / 8];   // 64MB as half
__device__ float4 g_B[(size_t)3072  * DM / 8];   // 12MB as half
__device__ float2 g_rope[TLEN * 64];

// ---------------- helpers ----------------
__device__ __forceinline__ uint32_t smem_u32(const void* p) {
    uint32_t a;
    asm("{ .reg .u64 t; cvta.to.shared.u64 t, %1; cvt.u32.u64 %0, t; }" : "=r"(a) : "l"(p));
    return a;
}
__device__ __forceinline__ void cp16(uint32_t dst, const void* src) {
    asm volatile("cp.async.cg.shared.global [%0], [%1], 16;" :: "r"(dst), "l"(src));
}
#define LDSM4(r0,r1,r2,r3,addr) \
    asm volatile("ldmatrix.sync.aligned.m8n8.x4.shared.b16 {%0,%1,%2,%3}, [%4];" \
                 : "=r"(r0), "=r"(r1), "=r"(r2), "=r"(r3) : "r"(addr))
__device__ __forceinline__ void mma16(float* c, const uint32_t* a, uint32_t b0, uint32_t b1) {
    asm volatile(
        "mma.sync.aligned.m16n8k16.row.col.f32.f16.f16.f32 "
        "{%0,%1,%2,%3}, {%4,%5,%6,%7}, {%8,%9}, {%0,%1,%2,%3};"
        : "+f"(c[0]), "+f"(c[1]), "+f"(c[2]), "+f"(c[3])
        : "r"(a[0]), "r"(a[1]), "r"(a[2]), "r"(a[3]), "r"(b0), "r"(b1));
}
__device__ __forceinline__ uint2 cvt4(float4 v) {
    __half2 h0 = __floats2half2_rn(v.x, v.y);
    __half2 h1 = __floats2half2_rn(v.z, v.w);
    uint2 o;
    o.x = *reinterpret_cast<uint32_t*>(&h0);
    o.y = *reinterpret_cast<uint32_t*>(&h1);
    return o;
}

// ---------------- merged prelude: cvtx | cvtw | rope in one launch ----------------
__global__ void __launch_bounds__(512)
k_pre(const float4* __restrict__ x, const float4* __restrict__ wq,
      const float4* __restrict__ wk, const float4* __restrict__ wv,
      const int* __restrict__ po) {
    const int b = blockIdx.x, tid = threadIdx.x;
    if (b < 4096) {
        uint2* d = (uint2*)g_A;
        int i0 = (b * 512 + tid) * 4;                 // covers 8388608 exactly
        float4 v0 = x[i0], v1 = x[i0 + 1], v2 = x[i0 + 2], v3 = x[i0 + 3];
        d[i0] = cvt4(v0); d[i0 + 1] = cvt4(v1); d[i0 + 2] = cvt4(v2); d[i0 + 3] = cvt4(v3);
    } else if (b < 5632) {
        uint2* d = (uint2*)g_B;
        int i0 = (b - 4096) * 1024 + tid * 2;         // covers 1572864 exactly
#pragma unroll
        for (int u = 0; u < 2; u++) {
            int i = i0 + u, j = i;
            const float4* s;
            if (i < 1048576)      { s = wq; }
            else if (i < 1310720) { s = wk; j = i - 1048576; }
            else                  { s = wv; j = i - 1310720; }
            d[i] = cvt4(s[j]);
        }
    } else {
        int idx = (b - 5632) * 512 + tid;             // 524288 = 8192*64
        int t = idx >> 6, j = idx & 63;
        float invf = exp2f(-(float)j * 0.20762050593046013f);   // log2(10000)/64
        float ang = (float)(t + *po) * invf;
        float k = rintf(ang * 0.15915494309189535f);
        float r = fmaf(-k, 6.28125f, ang);
        r = fmaf(-k, (float)(6.283185307179586 - 6.28125), r);
        float s, c;
        sincosf(r, &s, &c);
        g_rope[t * 64 + j] = make_float2(c, s);
    }
}

// ---------------- stage fill: one 64-wide K chunk (fp16) ----------------
__device__ __forceinline__ void fill_stage(int tid, const __half* Ab, const __half* Bb,
                                           uint32_t sb, int chunk) {
    const int kof = chunk * BK;
#pragma unroll
    for (int i = 0; i < 4; i++) {                // A: 128 rows x 8 segs
        int id = i * 256 + tid;
        int r = id >> 3, seg = id & 7;
        uint32_t off = (uint32_t)(r * 128) + (uint32_t)((seg * 16) ^ ((r & 7) << 4));
        cp16(sb + off, Ab + (size_t)r * DM + kof + seg * 8);
    }
#pragma unroll
    for (int i = 0; i < 4; i++) {                // B: 128 rows x 8 segs
        int id = i * 256 + tid;
        int r = id >> 3, seg = id & 7;
        uint32_t off = (uint32_t)(r * 128) + (uint32_t)((seg * 16) ^ ((r & 7) << 4));
        cp16(sb + 16384u + off, Bb + (size_t)r * DM + kof + seg * 8);
    }
    asm volatile("cp.async.commit_group;" ::: "memory");
}

// ---------------- main GEMM + in-register RoPE epilogue ----------------
__global__ void __launch_bounds__(256, 2)
k_gemm(float* __restrict__ out) {
    extern __shared__ float sm[];
    const uint32_t smb = smem_u32(sm);
    const int tid = threadIdx.x;
    const int lane = tid & 31, wid = tid >> 5;      // 8 warps
    const int q = lane >> 2, t4 = lane & 3;
    const int mw = (wid >> 2) * 64;                 // warp M base (64 rows)
    const int nwl = (wid & 3) * 16;                 // warp N strip: [nwl,nwl+16) U [+64,+80)
    const int nt = blockIdx.x, mt = blockIdx.y;

    const __half* Ab = (const __half*)g_A + (size_t)mt * BM * DM;
    const __half* Bb = (const __half*)g_B + (size_t)nt * BN * DM;

    float acc[4][4][4];
#pragma unroll
    for (int i = 0; i < 4; i++)
#pragma unroll
        for (int j = 0; j < 4; j++)
#pragma unroll
            for (int r = 0; r < 4; r++) acc[i][j][r] = 0.f;

    fill_stage(tid, Ab, Bb, smb, 0);
    fill_stage(tid, Ab, Bb, smb + STG_BYTES, 1);
    fill_stage(tid, Ab, Bb, smb + 2 * STG_BYTES, 2);

    // per-lane ldmatrix source rows/segs
    const int arow = mw + (lane & 15);                       // + mi*16
    const int alds = (lane >> 4);                            // k-seg +0/+1
    const int brow = nwl + ((lane >> 4) << 3) + (lane & 7);  // + np*64 (split strips!)
    const int blds = ((lane >> 3) & 1);

    for (int k = 0; k < NCHUNK; k++) {
        const int s = k % 3;
        const int rem = (NCHUNK - 1) - k;
        if (rem >= 2)      asm volatile("cp.async.wait_group 2;" ::: "memory");
        else if (rem == 1) asm volatile("cp.async.wait_group 1;" ::: "memory");
        else               asm volatile("cp.async.wait_group 0;" ::: "memory");
        __syncthreads();

        const uint32_t Asb = smb + (uint32_t)s * STG_BYTES;
        const uint32_t Bsb = Asb + 16384u;
#pragma unroll
        for (int ks = 0; ks < 4; ks++) {
            const uint32_t asw = (uint32_t)(((ks * 2 + alds) * 16) ^ ((arow & 7) << 4));
            const uint32_t bsw = (uint32_t)(((ks * 2 + blds) * 16) ^ ((brow & 7) << 4));
            uint32_t a[4][4], b[4][2];
#pragma unroll
            for (int mi = 0; mi < 4; mi++) {
                uint32_t ad = Asb + (uint32_t)((arow + mi * 16) * 128) + asw;
                LDSM4(a[mi][0], a[mi][1], a[mi][2], a[mi][3], ad);
            }
#pragma unroll
            for (int np = 0; np < 2; np++) {       // strip np: B rows nwl + np*64 + {0..15}
                uint32_t bd = Bsb + (uint32_t)((brow + np * 64) * 128) + bsw;
                LDSM4(b[2*np][0], b[2*np][1], b[2*np+1][0], b[2*np+1][1], bd);
            }
#pragma unroll
            for (int mi = 0; mi < 4; mi++)
#pragma unroll
                for (int ni = 0; ni < 4; ni++)
                    mma16(acc[mi][ni], a[mi], b[ni][0], b[ni][1]);
        }
        __syncthreads();
        if (k + 3 < NCHUNK) fill_stage(tid, Ab, Bb, smb + (uint32_t)((k + 3) % 3) * STG_BYTES, k + 3);
    }

    // ---- in-register RoPE + direct stores ----
    // acc[mi][sub8]     -> cols nwl + sub8*8 + 2t4      (d in [0,64))
    // acc[mi][2+sub8]   -> cols nwl + 64 + sub8*8 + 2t4 (d+64)
    const bool ropef = (nt < 20);
#pragma unroll
    for (int mi = 0; mi < 4; mi++) {
#pragma unroll
        for (int rr = 0; rr < 2; rr++) {
            const int row = mw + mi * 16 + q + rr * 8;
            const int gm = mt * BM + row;
            const int bb = gm >> 13, tt = gm & (TLEN - 1);
            size_t obase;
            if (nt < 16)      obase = ((size_t)(bb * 16 + nt) * TLEN + tt) * 128;
            else if (nt < 20) obase = QSZ + ((size_t)(bb * 4 + (nt - 16)) * TLEN + tt) * 128;
            else              obase = QSZ + KSZ + ((size_t)(bb * 4 + (nt - 20)) * TLEN + tt) * 128;
            float* op = out + obase;
            const float2* rp = g_rope + (size_t)tt * 64;
#pragma unroll
            for (int sub8 = 0; sub8 < 2; sub8++) {
                const int d = nwl + sub8 * 8 + 2 * t4;
                float xl0 = acc[mi][sub8][rr * 2],     xl1 = acc[mi][sub8][rr * 2 + 1];
                float xh0 = acc[mi][2 + sub8][rr * 2], xh1 = acc[mi][2 + sub8][rr * 2 + 1];
                float2 lo, hi;
                if (ropef) {
                    const float2 cs0 = rp[d], cs1 = rp[d + 1];
                    lo.x = xl0 * cs0.x - xh0 * cs0.y;  hi.x = xh0 * cs0.x + xl0 * cs0.y;
                    lo.y = xl1 * cs1.x - xh1 * cs1.y;  hi.y = xh1 * cs1.x + xl1 * cs1.y;
                } else {
                    lo.x = xl0; lo.y = xl1; hi.x = xh0; hi.y = xh1;
                }
                *(float2*)&op[d]      = lo;
                *(float2*)&op[d + 64] = hi;
            }
        }
    }
}

// ---------------- launch ----------------
extern "C" void kernel_launch(void* const* d_in, const int* in_sizes, int n_in,
                              void* d_out, int out_size) {
    const float* x  = (const float*)d_in[0];
    const float* wq = (const float*)d_in[1];
    const float* wk = (const float*)d_in[2];
    const float* wv = (const float*)d_in[3];
    const int*   po = (const int*)d_in[4];
    float* out = (float*)d_out;

    k_pre<<<6656, 512>>>((const float4*)x, (const float4*)wq,
                         (const float4*)wk, (const float4*)wv, po);

    cudaFuncSetAttribute(k_gemm, cudaFuncAttributeMaxDynamicSharedMemorySize, SMEM_BYTES);
    k_gemm<<<dim3(24, 128, 1), 256, SMEM_BYTES>>>(out);
    (void)in_sizes; (void)n_in; (void)out_size;
}